// round 15
// baseline (speedup 1.0000x reference)
#include <cuda_runtime.h>
#include <cuda_bf16.h>
#include <cstdint>

#define NATOMS 50000
#define FDIM 128
#define KDIM 64
#define NB 5
#define NRI 3
#define NRF 2
#define NWMAT 65   // 5 Wi + 5 Wj + 15 Wr1 + 15 Wr2 + 5 Wout + 10 Wf1 + 10 Wf2

// Scratch (allocation-free rule: __device__ globals)
__device__ float g_xj[NATOMS * FDIM];
__device__ float g_m [NATOMS * FDIM];
// Per-lane prepacked B fragments: [slot][s(8)][t(16)][lane(32)] = uint4{bhi0,bhi1,blo0,blo1}
__device__ uint4 g_wfrag[(size_t)NWMAT * 4096];
// Wg fragments: [slot(5)][s(4)][t(16)][lane(32)]
__device__ uint4 g_gfrag[(size_t)NB * 2048];

__device__ __forceinline__ float sspf(float x) {
    return fmaxf(x, 0.0f) + log1pf(expf(-fabsf(x))) - 0.69314718055994530942f;
}

// ---- bf16x2 pack: low 16 bits = bf16(lo), high = bf16(hi) ----
__device__ __forceinline__ uint32_t pack_bf(float lo, float hi) {
    uint32_t r;
    asm("cvt.rn.bf16x2.f32 %0, %1, %2;" : "=r"(r) : "f"(hi), "f"(lo));
    return r;
}
// split float2 -> bf16x2 hi fragment + bf16x2 lo (residual) fragment
__device__ __forceinline__ void split2(float a, float b, uint32_t& h, uint32_t& l) {
    h = pack_bf(a, b);
    float h0 = __uint_as_float(h << 16);
    float h1 = __uint_as_float(h & 0xFFFF0000u);
    l = pack_bf(a - h0, b - h1);
}

// m16n8k16 row.col f32.bf16.bf16.f32
#define MMA_BF16(d0, d1, d2, d3, a0, a1, a2, a3, b0, b1)                     \
    asm volatile("mma.sync.aligned.m16n8k16.row.col.f32.bf16.bf16.f32 "      \
                 "{%0,%1,%2,%3},{%4,%5,%6,%7},{%8,%9},{%0,%1,%2,%3};"        \
                 : "+f"(d0), "+f"(d1), "+f"(d2), "+f"(d3)                    \
                 : "r"(a0), "r"(a1), "r"(a2), "r"(a3), "r"(b0), "r"(b1))

// 3-term split MMA with INDEPENDENT accumulator quads (3x MMA ILP):
//   e += AH*Bhi,  f += AL*Bhi,  h += AH*Blo
#define MMA3S(E, F, H, AH, AL, b)                                                 \
    do {                                                                          \
        MMA_BF16(E[0], E[1], E[2], E[3], AH[0], AH[1], AH[2], AH[3], (b).x, (b).y);\
        MMA_BF16(F[0], F[1], F[2], F[3], AL[0], AL[1], AL[2], AL[3], (b).x, (b).y);\
        MMA_BF16(H[0], H[1], H[2], H[3], AH[0], AH[1], AH[2], AH[3], (b).z, (b).w);\
    } while (0)

#define ACC_DECL(E, F, H)                                                  \
    float E[4] = {0.f, 0.f, 0.f, 0.f};                                     \
    float F[4] = {0.f, 0.f, 0.f, 0.f};                                     \
    float H[4] = {0.f, 0.f, 0.f, 0.f}

#define ACC_SUM(d0, d1, d2, d3, E, F, H)                                   \
    float d0 = (E[0] + F[0]) + H[0];                                       \
    float d1 = (E[1] + F[1]) + H[1];                                       \
    float d2 = (E[2] + F[2]) + H[2];                                       \
    float d3 = (E[3] + F[3]) + H[3]

// named barriers (producer/consumer handshake)
#define BAR_SYNC(id, cnt)   asm volatile("bar.sync %0, %1;"   :: "r"(id), "r"(cnt) : "memory")
#define BAR_ARRIVE(id, cnt) asm volatile("bar.arrive %0, %1;" :: "r"(id), "r"(cnt) : "memory")

// ---------------------------------------------------------------------------
// Weight prepasses
// ---------------------------------------------------------------------------
__global__ void wfrag_k(const float* __restrict__ Wi, const float* __restrict__ Wj,
                        const float* __restrict__ Wr1, const float* __restrict__ Wr2,
                        const float* __restrict__ Wout, const float* __restrict__ Wf1,
                        const float* __restrict__ Wf2)
{
    int slot = blockIdx.y;
    const float* src;
    if (slot < 5)       src = Wi   + (size_t)slot * 16384;
    else if (slot < 10) src = Wj   + (size_t)(slot - 5) * 16384;
    else if (slot < 25) src = Wr1  + (size_t)(slot - 10) * 16384;
    else if (slot < 40) src = Wr2  + (size_t)(slot - 25) * 16384;
    else if (slot < 45) src = Wout + (size_t)(slot - 40) * 16384;
    else if (slot < 55) src = Wf1  + (size_t)(slot - 45) * 16384;
    else                src = Wf2  + (size_t)(slot - 55) * 16384;

    int q = blockIdx.x * 128 + threadIdx.x;   // 0..4095
    int l = q & 31, t = (q >> 5) & 15, s = q >> 9;
    int n = 8 * t + (l >> 2);
    int k0 = 16 * s + 2 * (l & 3);

    float w0 = src[(k0 + 0) * 128 + n];
    float w1 = src[(k0 + 1) * 128 + n];
    float w8 = src[(k0 + 8) * 128 + n];
    float w9 = src[(k0 + 9) * 128 + n];
    uint4 o;
    split2(w0, w1, o.x, o.z);
    split2(w8, w9, o.y, o.w);
    g_wfrag[(size_t)slot * 4096 + q] = o;
}

__global__ void wgfrag_k(const float* __restrict__ Wg)
{
    int slot = blockIdx.y;
    const float* src = Wg + (size_t)slot * KDIM * FDIM;
    int q = blockIdx.x * 128 + threadIdx.x;   // 0..2047
    int l = q & 31, t = (q >> 5) & 15, s = q >> 9;   // s 0..3
    int n = 8 * t + (l >> 2);
    int k0 = 16 * s + 2 * (l & 3);
    float w0 = src[(k0 + 0) * 128 + n];
    float w1 = src[(k0 + 1) * 128 + n];
    float w8 = src[(k0 + 8) * 128 + n];
    float w9 = src[(k0 + 9) * 128 + n];
    uint4 o;
    split2(w0, w1, o.x, o.z);
    split2(w8, w9, o.y, o.w);
    g_gfrag[(size_t)slot * 2048 + q] = o;
}

// ---------------------------------------------------------------------------
// Fused xi/xj GEMM
// ---------------------------------------------------------------------------
__global__ __launch_bounds__(128, 2)
void tmma2_k(const float* __restrict__ X,
             const uint4* __restrict__ WF1, const float* __restrict__ b1, float* __restrict__ Y1,
             const uint4* __restrict__ WF2, const float* __restrict__ b2, float* __restrict__ Y2,
             int M)
{
    const int tid = threadIdx.x;
    const int w = tid >> 5, l = tid & 31;
    const int c = l & 3, g = l >> 2;
    const int r0 = blockIdx.x * 64 + w * 16 + g;
    const int r1 = r0 + 8;
    const float* xr0 = X + (size_t)min(r0, M - 1) * FDIM;
    const float* xr1 = X + (size_t)min(r1, M - 1) * FDIM;

    uint32_t ahi[8][4], alo[8][4];
#pragma unroll
    for (int s = 0; s < 8; s++) {
        int col0 = 16 * s + 2 * c;
        float2 v00 = *(const float2*)(xr0 + col0);
        float2 v10 = *(const float2*)(xr1 + col0);
        float2 v01 = *(const float2*)(xr0 + col0 + 8);
        float2 v11 = *(const float2*)(xr1 + col0 + 8);
        v00.x = sspf(v00.x); v00.y = sspf(v00.y);
        v10.x = sspf(v10.x); v10.y = sspf(v10.y);
        v01.x = sspf(v01.x); v01.y = sspf(v01.y);
        v11.x = sspf(v11.x); v11.y = sspf(v11.y);
        split2(v00.x, v00.y, ahi[s][0], alo[s][0]);
        split2(v10.x, v10.y, ahi[s][1], alo[s][1]);
        split2(v01.x, v01.y, ahi[s][2], alo[s][2]);
        split2(v11.x, v11.y, ahi[s][3], alo[s][3]);
    }

    const bool ok0 = (r0 < M), ok1 = (r1 < M);

#pragma unroll
    for (int m = 0; m < 2; m++) {
        const uint4* WF = m ? WF2 : WF1;
        const float* bias = m ? b2 : b1;
        float* Y = m ? Y2 : Y1;
#pragma unroll
        for (int t = 0; t < 16; t++) {
            ACC_DECL(e, f, h);
#pragma unroll
            for (int s = 0; s < 8; s++) {
                uint4 b = WF[(size_t)((s * 16 + t) * 32 + l)];
                MMA3S(e, f, h, ahi[s], alo[s], b);
            }
            ACC_SUM(d0, d1, d2, d3, e, f, h);
            const int col = 8 * t + 2 * c;
            float2 bv = *(const float2*)(bias + col);
            float2 o0, o1;
            o0.x = sspf(d0 + bv.x); o0.y = sspf(d1 + bv.y);
            o1.x = sspf(d2 + bv.x); o1.y = sspf(d3 + bv.y);
            if (ok0) *(float2*)(Y + (size_t)r0 * FDIM + col) = o0;
            if (ok1) *(float2*)(Y + (size_t)r1 * FDIM + col) = o1;
        }
    }
}

// ---------------------------------------------------------------------------
// Tensor-core GEMM: EPI=0 ssp, EPI=2 gated skip
// ---------------------------------------------------------------------------
template <int PRE, int EPI>
__global__ __launch_bounds__(128, 2)
void tmma_k(const float* __restrict__ X, const uint4* __restrict__ WF,
            const float* __restrict__ bias, const float* __restrict__ R,
            const float* __restrict__ U, float* __restrict__ Y, int M)
{
    const int tid = threadIdx.x;
    const int w = tid >> 5, l = tid & 31;
    const int c = l & 3, g = l >> 2;
    const int r0 = blockIdx.x * 64 + w * 16 + g;
    const int r1 = r0 + 8;
    const float* xr0 = X + (size_t)min(r0, M - 1) * FDIM;
    const float* xr1 = X + (size_t)min(r1, M - 1) * FDIM;

    uint32_t ahi[8][4], alo[8][4];
#pragma unroll
    for (int s = 0; s < 8; s++) {
        int col0 = 16 * s + 2 * c;
        float2 v00 = *(const float2*)(xr0 + col0);
        float2 v10 = *(const float2*)(xr1 + col0);
        float2 v01 = *(const float2*)(xr0 + col0 + 8);
        float2 v11 = *(const float2*)(xr1 + col0 + 8);
        if (PRE) {
            v00.x = sspf(v00.x); v00.y = sspf(v00.y);
            v10.x = sspf(v10.x); v10.y = sspf(v10.y);
            v01.x = sspf(v01.x); v01.y = sspf(v01.y);
            v11.x = sspf(v11.x); v11.y = sspf(v11.y);
        }
        split2(v00.x, v00.y, ahi[s][0], alo[s][0]);
        split2(v10.x, v10.y, ahi[s][1], alo[s][1]);
        split2(v01.x, v01.y, ahi[s][2], alo[s][2]);
        split2(v11.x, v11.y, ahi[s][3], alo[s][3]);
    }

    const bool ok0 = (r0 < M), ok1 = (r1 < M);

#pragma unroll
    for (int t = 0; t < 16; t++) {
        ACC_DECL(e, f, h);
#pragma unroll
        for (int s = 0; s < 8; s++) {
            uint4 b = WF[(size_t)((s * 16 + t) * 32 + l)];
            MMA3S(e, f, h, ahi[s], alo[s], b);
        }
        ACC_SUM(d0, d1, d2, d3, e, f, h);
        const int col = 8 * t + 2 * c;
        float2 bv = *(const float2*)(bias + col);
        d0 += bv.x; d1 += bv.y; d2 += bv.x; d3 += bv.y;

        float2 o0, o1;
        if (EPI == 0) {
            o0.x = sspf(d0); o0.y = sspf(d1);
            o1.x = sspf(d2); o1.y = sspf(d3);
        } else {
            float2 uv = *(const float2*)(U + col);
            float2 rv0 = ok0 ? *(const float2*)(R + (size_t)r0 * FDIM + col) : make_float2(0.f, 0.f);
            float2 rv1 = ok1 ? *(const float2*)(R + (size_t)r1 * FDIM + col) : make_float2(0.f, 0.f);
            o0.x = fmaf(uv.x, rv0.x, d0); o0.y = fmaf(uv.y, rv0.y, d1);
            o1.x = fmaf(uv.x, rv1.x, d2); o1.y = fmaf(uv.y, rv1.y, d3);
        }
        if (ok0) *(float2*)(Y + (size_t)r0 * FDIM + col) = o0;
        if (ok1) *(float2*)(Y + (size_t)r1 * FDIM + col) = o1;
    }
}

// ---------------------------------------------------------------------------
// Fused residual layer: Y = X + ssp(ssp(X)@W1+b1)@W2 + b2   (Y may alias X)
// ---------------------------------------------------------------------------
__global__ __launch_bounds__(128, 2)
void rsd_k(const float* __restrict__ X,
           const uint4* __restrict__ WF1, const float* __restrict__ b1,
           const uint4* __restrict__ WF2, const float* __restrict__ b2,
           float* __restrict__ Y, int M)
{
    const int tid = threadIdx.x;
    const int w = tid >> 5, l = tid & 31;
    const int c = l & 3, g = l >> 2;
    const int r0 = blockIdx.x * 64 + w * 16 + g;
    const int r1 = r0 + 8;
    const float* xr0 = X + (size_t)min(r0, M - 1) * FDIM;
    const float* xr1 = X + (size_t)min(r1, M - 1) * FDIM;

    uint32_t ahi[8][4], alo[8][4];
#pragma unroll
    for (int s = 0; s < 8; s++) {
        int col0 = 16 * s + 2 * c;
        float2 v00 = *(const float2*)(xr0 + col0);
        float2 v10 = *(const float2*)(xr1 + col0);
        float2 v01 = *(const float2*)(xr0 + col0 + 8);
        float2 v11 = *(const float2*)(xr1 + col0 + 8);
        v00.x = sspf(v00.x); v00.y = sspf(v00.y);
        v10.x = sspf(v10.x); v10.y = sspf(v10.y);
        v01.x = sspf(v01.x); v01.y = sspf(v01.y);
        v11.x = sspf(v11.x); v11.y = sspf(v11.y);
        split2(v00.x, v00.y, ahi[s][0], alo[s][0]);
        split2(v10.x, v10.y, ahi[s][1], alo[s][1]);
        split2(v01.x, v01.y, ahi[s][2], alo[s][2]);
        split2(v11.x, v11.y, ahi[s][3], alo[s][3]);
    }

    // GEMM1 with immediate repack of ssp(z) pairs into GEMM2 A-fragments
    uint32_t zhi[8][4], zlo[8][4];
    float zb0 = 0.f, zb1 = 0.f, zb2 = 0.f, zb3 = 0.f;
#pragma unroll
    for (int t = 0; t < 16; t++) {
        ACC_DECL(e, f, h);
#pragma unroll
        for (int s = 0; s < 8; s++) {
            uint4 b = WF1[(size_t)((s * 16 + t) * 32 + l)];
            MMA3S(e, f, h, ahi[s], alo[s], b);
        }
        ACC_SUM(d0, d1, d2, d3, e, f, h);
        const int col = 8 * t + 2 * c;
        float2 bv = *(const float2*)(b1 + col);
        d0 = sspf(d0 + bv.x); d1 = sspf(d1 + bv.y);
        d2 = sspf(d2 + bv.x); d3 = sspf(d3 + bv.y);
        if ((t & 1) == 0) {
            zb0 = d0; zb1 = d1; zb2 = d2; zb3 = d3;
        } else {
            const int s2 = t >> 1;
            split2(zb0, zb1, zhi[s2][0], zlo[s2][0]);
            split2(zb2, zb3, zhi[s2][1], zlo[s2][1]);
            split2(d0, d1, zhi[s2][2], zlo[s2][2]);
            split2(d2, d3, zhi[s2][3], zlo[s2][3]);
        }
    }

    const bool ok0 = (r0 < M), ok1 = (r1 < M);

    // GEMM2 + residual epilogue
#pragma unroll
    for (int t = 0; t < 16; t++) {
        ACC_DECL(e, f, h);
#pragma unroll
        for (int s = 0; s < 8; s++) {
            uint4 b = WF2[(size_t)((s * 16 + t) * 32 + l)];
            MMA3S(e, f, h, zhi[s], zlo[s], b);
        }
        ACC_SUM(d0, d1, d2, d3, e, f, h);
        const int col = 8 * t + 2 * c;
        float2 bv = *(const float2*)(b2 + col);
        float2 rv0 = ok0 ? *(const float2*)(X + (size_t)r0 * FDIM + col) : make_float2(0.f, 0.f);
        float2 rv1 = ok1 ? *(const float2*)(X + (size_t)r1 * FDIM + col) : make_float2(0.f, 0.f);
        float2 o0, o1;
        o0.x = rv0.x + d0 + bv.x; o0.y = rv0.y + d1 + bv.y;
        o1.x = rv1.x + d2 + bv.x; o1.y = rv1.y + d3 + bv.y;
        if (ok0) *(float2*)(Y + (size_t)r0 * FDIM + col) = o0;
        if (ok1) *(float2*)(Y + (size_t)r1 * FDIM + col) = o1;
    }
}

// ---------------------------------------------------------------------------
// Warp-specialized message pass: 256 threads.
//   warps 0-3 (producer): stage desc, MMA filter -> gsm[buf] (double-buffered)
//   warps 4-7 (consumer): thread = feature; gathers issued BEFORE waiting on
//   full-barrier (hidden under producer MMA), then segment accumulate.
// Named barriers: full{0,1} = 1,2 ; empty{0,1} = 3,4 ; producer-internal = 5.
// ---------------------------------------------------------------------------
#define MSG_PPB 512
#define DESC_P 68
#define GSM_P 132

__global__ __launch_bounds__(256)
void msgmma_k(const float* __restrict__ cutoffs, const float* __restrict__ rbfs,
              const int* __restrict__ idx_i, const int* __restrict__ idx_j,
              const uint4* __restrict__ GF, const float* __restrict__ xj,
              float* __restrict__ m, int npairs)
{
    __shared__ __align__(16) float desc[32][DESC_P];
    __shared__ __align__(16) float gsm[2][32][GSM_P];

    const int tid = threadIdx.x;
    const int p0 = blockIdx.x * MSG_PPB;
    const int pend = min(p0 + MSG_PPB, npairs);

    if (tid < 128) {
        // ------------------------ producer ------------------------
        const int t = tid;
        const int w = t >> 5, l = t & 31;
        const int c = l & 3, g = l >> 2;
        int chunk = 0;
        for (int base = p0; base < pend; base += 32, chunk++) {
            const int b = chunk & 1;
            const int ns = min(32, pend - base);
            if (chunk >= 2) BAR_SYNC(3 + b, 256);     // gsm[b] consumed

            // stage desc = cutoff * rbf
            for (int li = t; li < ns * 16; li += 128) {
                int s = li >> 4, v = li & 15;
                float cf = cutoffs[base + s];
                float4 r = *(const float4*)&rbfs[(size_t)(base + s) * KDIM + v * 4];
                r.x *= cf; r.y *= cf; r.z *= cf; r.w *= cf;
                *(float4*)&desc[s][v * 4] = r;
            }
            BAR_SYNC(5, 128);                          // desc visible to producers

            // frag build (2 m-tiles x 4 k-steps)
            uint32_t ahi[2][4][4], alo[2][4][4];
#pragma unroll
            for (int mt = 0; mt < 2; mt++) {
                int rg = mt * 16 + g;
#pragma unroll
                for (int s = 0; s < 4; s++) {
                    int k0 = 16 * s + 2 * c;
                    float2 v00 = *(const float2*)&desc[rg][k0];
                    float2 v10 = *(const float2*)&desc[rg + 8][k0];
                    float2 v01 = *(const float2*)&desc[rg][k0 + 8];
                    float2 v11 = *(const float2*)&desc[rg + 8][k0 + 8];
                    split2(v00.x, v00.y, ahi[mt][s][0], alo[mt][s][0]);
                    split2(v10.x, v10.y, ahi[mt][s][1], alo[mt][s][1]);
                    split2(v01.x, v01.y, ahi[mt][s][2], alo[mt][s][2]);
                    split2(v11.x, v11.y, ahi[mt][s][3], alo[mt][s][3]);
                }
            }
            // MMA: warp w covers n-tiles 4w..4w+3
#pragma unroll
            for (int j = 0; j < 4; j++) {
                const int tt = 4 * w + j;
                const int col = 8 * tt + 2 * c;
#pragma unroll
                for (int mt = 0; mt < 2; mt++) {
                    ACC_DECL(e, f, h);
#pragma unroll
                    for (int s = 0; s < 4; s++) {
                        uint4 bb = GF[(size_t)((s * 16 + tt) * 32 + l)];
                        MMA3S(e, f, h, ahi[mt][s], alo[mt][s], bb);
                    }
                    ACC_SUM(d0, d1, d2, d3, e, f, h);
                    int rg = mt * 16 + g;
                    *(float2*)&gsm[b][rg][col] = make_float2(d0, d1);
                    *(float2*)&gsm[b][rg + 8][col] = make_float2(d2, d3);
                }
            }
            BAR_ARRIVE(1 + b, 256);                    // gsm[b] full
            BAR_SYNC(5, 128);                          // all producers done with desc
        }
    } else {
        // ------------------------ consumer ------------------------
        const int t = tid - 128;                       // feature index
        const int lane = t & 31;
        float acc = 0.0f;
        int prev = -1;
        int chunk = 0;
        for (int base = p0; base < pend; base += 32, chunk++) {
            const int b = chunk & 1;
            const int ns = min(32, pend - base);
            // load indices + issue gathers BEFORE waiting (overlap producer MMA)
            const int gi = base + min(lane, ns - 1);
            int sjr = idx_j[gi];
            int sir = idx_i[gi];
            float xv[32];
#pragma unroll
            for (int s = 0; s < 32; s++) {
                int j = __shfl_sync(0xFFFFFFFFu, sjr, s);
                xv[s] = xj[(size_t)j * FDIM + t];
            }
            BAR_SYNC(1 + b, 256);                      // wait gsm[b] full
#pragma unroll
            for (int s = 0; s < 32; s++) {
                if (s < ns) {
                    int i = __shfl_sync(0xFFFFFFFFu, sir, s);
                    if (i != prev) {
                        if (prev >= 0) atomicAdd(&m[(size_t)prev * FDIM + t], acc);
                        acc = 0.0f;
                        prev = i;
                    }
                    acc = fmaf(gsm[b][s][t], xv[s], acc);
                }
            }
            BAR_ARRIVE(3 + b, 256);                    // gsm[b] empty
        }
        if (prev >= 0) atomicAdd(&m[(size_t)prev * FDIM + t], acc);
    }
}

// ---------------------------------------------------------------------------
extern "C" void kernel_launch(void* const* d_in, const int* in_sizes, int n_in,
                              void* d_out, int out_size)
{
    const float* features = (const float*)d_in[0];
    const float* cutoffs  = (const float*)d_in[1];
    const float* rbfs     = (const float*)d_in[2];
    const int*   idx_i    = (const int*)d_in[3];
    const int*   idx_j    = (const int*)d_in[4];
    const float* Wg   = (const float*)d_in[5];
    const float* bi   = (const float*)d_in[7];
    const float* bj   = (const float*)d_in[9];
    const float* br1  = (const float*)d_in[11];
    const float* br2  = (const float*)d_in[13];
    const float* bout = (const float*)d_in[15];
    const float* u    = (const float*)d_in[16];
    const float* bf1  = (const float*)d_in[18];
    const float* bf2  = (const float*)d_in[20];
    const int npairs = in_sizes[1];
    float* out = (float*)d_out;

    float *xjp, *mp;
    uint4 *wfrag, *gfrag;
    cudaGetSymbolAddress((void**)&xjp, g_xj);
    cudaGetSymbolAddress((void**)&mp,  g_m);
    cudaGetSymbolAddress((void**)&wfrag, g_wfrag);
    cudaGetSymbolAddress((void**)&gfrag, g_gfrag);

    const int gemmGrid = (NATOMS + 63) / 64;
    const int msgGrid = (npairs + MSG_PPB - 1) / MSG_PPB;

    // prepasses (cheap; once per launch)
    wfrag_k<<<dim3(32, NWMAT), 128>>>((const float*)d_in[6], (const float*)d_in[8],
                                      (const float*)d_in[10], (const float*)d_in[12],
                                      (const float*)d_in[14], (const float*)d_in[17],
                                      (const float*)d_in[19]);
    wgfrag_k<<<dim3(16, NB), 128>>>(Wg);

    auto WFr = [&](int slot) { return wfrag + (size_t)slot * 4096; };

    const float* x = features;
    for (int b = 0; b < NB; b++) {
        float* xout = out + (size_t)b * NATOMS * FDIM;

        // m = xi = ssp(ssp(x)@Wi+bi);  xj = ssp(ssp(x)@Wj+bj)   (fused)
        tmma2_k<<<gemmGrid, 128>>>(x, WFr(b), bi + b * FDIM, mp,
                                   WFr(5 + b), bj + b * FDIM, xjp, NATOMS);
        // m += segment_sum( (desc @ Wg) * xj[idx_j], idx_i )  (warp-specialized)
        msgmma_k<<<msgGrid, 256>>>(cutoffs, rbfs, idx_i, idx_j,
                                   gfrag + (size_t)b * 2048, xjp, mp, npairs);
        // interaction residuals (fused pairs, in-place)
        for (int r = 0; r < NRI; r++) {
            int s1 = 10 + b * NRI + r, s2 = 25 + b * NRI + r;
            rsd_k<<<gemmGrid, 128>>>(mp, WFr(s1), br1 + (size_t)(b * NRI + r) * FDIM,
                                     WFr(s2), br2 + (size_t)(b * NRI + r) * FDIM, mp, NATOMS);
        }
        // x' = u*x + ssp(m) @ Wout + bout
        tmma_k<1, 2><<<gemmGrid, 128>>>(mp, WFr(40 + b), bout + b * FDIM,
                                        x, u + b * FDIM, xout, NATOMS);
        // feature residuals (fused pairs, in-place on output slab)
        for (int r = 0; r < NRF; r++) {
            int s1 = 45 + b * NRF + r, s2 = 55 + b * NRF + r;
            rsd_k<<<gemmGrid, 128>>>(xout, WFr(s1), bf1 + (size_t)(b * NRF + r) * FDIM,
                                     WFr(s2), bf2 + (size_t)(b * NRF + r) * FDIM, xout, NATOMS);
        }
        x = xout;
    }
}

// round 16
// speedup vs baseline: 1.3790x; 1.3790x over previous
#include <cuda_runtime.h>
#include <cuda_bf16.h>
#include <cstdint>

#define NATOMS 50000
#define FDIM 128
#define KDIM 64
#define NB 5
#define NRI 3
#define NRF 2
#define NWMAT 65   // 5 Wi + 5 Wj + 15 Wr1 + 15 Wr2 + 5 Wout + 10 Wf1 + 10 Wf2

// Scratch (allocation-free rule: __device__ globals)
__device__ float g_xj[NATOMS * FDIM];
__device__ float g_m [NATOMS * FDIM];
// Per-lane prepacked B fragments: [slot][s(8)][t(16)][lane(32)] = uint4{bhi0,bhi1,blo0,blo1}
__device__ uint4 g_wfrag[(size_t)NWMAT * 4096];
// Wg fragments: [slot(5)][s(4)][t(16)][lane(32)]
__device__ uint4 g_gfrag[(size_t)NB * 2048];

__device__ __forceinline__ float sspf(float x) {
    return fmaxf(x, 0.0f) + log1pf(expf(-fabsf(x))) - 0.69314718055994530942f;
}

// ---- bf16x2 pack: low 16 bits = bf16(lo), high = bf16(hi) ----
__device__ __forceinline__ uint32_t pack_bf(float lo, float hi) {
    uint32_t r;
    asm("cvt.rn.bf16x2.f32 %0, %1, %2;" : "=r"(r) : "f"(hi), "f"(lo));
    return r;
}
// split float2 -> bf16x2 hi fragment + bf16x2 lo (residual) fragment
__device__ __forceinline__ void split2(float a, float b, uint32_t& h, uint32_t& l) {
    h = pack_bf(a, b);
    float h0 = __uint_as_float(h << 16);
    float h1 = __uint_as_float(h & 0xFFFF0000u);
    l = pack_bf(a - h0, b - h1);
}

// m16n8k16 row.col f32.bf16.bf16.f32
#define MMA_BF16(d0, d1, d2, d3, a0, a1, a2, a3, b0, b1)                     \
    asm volatile("mma.sync.aligned.m16n8k16.row.col.f32.bf16.bf16.f32 "      \
                 "{%0,%1,%2,%3},{%4,%5,%6,%7},{%8,%9},{%0,%1,%2,%3};"        \
                 : "+f"(d0), "+f"(d1), "+f"(d2), "+f"(d3)                    \
                 : "r"(a0), "r"(a1), "r"(a2), "r"(a3), "r"(b0), "r"(b1))

// 3-term split MMA, single accumulator (R12 proven config for atom path)
#define MMA3(d0, d1, d2, d3, AH, AL, b)                                          \
    do {                                                                         \
        MMA_BF16(d0, d1, d2, d3, AH[0], AH[1], AH[2], AH[3], (b).x, (b).y);      \
        MMA_BF16(d0, d1, d2, d3, AL[0], AL[1], AL[2], AL[3], (b).x, (b).y);      \
        MMA_BF16(d0, d1, d2, d3, AH[0], AH[1], AH[2], AH[3], (b).z, (b).w);      \
    } while (0)

// 2-quad variant for the msgmma producer (8+4 chains, +~16 regs only)
#define MMA3T(E, F, AH, AL, b)                                                    \
    do {                                                                          \
        MMA_BF16(E[0], E[1], E[2], E[3], AH[0], AH[1], AH[2], AH[3], (b).x, (b).y);\
        MMA_BF16(F[0], F[1], F[2], F[3], AL[0], AL[1], AL[2], AL[3], (b).x, (b).y);\
        MMA_BF16(E[0], E[1], E[2], E[3], AH[0], AH[1], AH[2], AH[3], (b).z, (b).w);\
    } while (0)

// named barriers (producer/consumer handshake)
#define BAR_SYNC(id, cnt)   asm volatile("bar.sync %0, %1;"   :: "r"(id), "r"(cnt) : "memory")
#define BAR_ARRIVE(id, cnt) asm volatile("bar.arrive %0, %1;" :: "r"(id), "r"(cnt) : "memory")

// ---------------------------------------------------------------------------
// Weight prepasses
// ---------------------------------------------------------------------------
__global__ void wfrag_k(const float* __restrict__ Wi, const float* __restrict__ Wj,
                        const float* __restrict__ Wr1, const float* __restrict__ Wr2,
                        const float* __restrict__ Wout, const float* __restrict__ Wf1,
                        const float* __restrict__ Wf2)
{
    int slot = blockIdx.y;
    const float* src;
    if (slot < 5)       src = Wi   + (size_t)slot * 16384;
    else if (slot < 10) src = Wj   + (size_t)(slot - 5) * 16384;
    else if (slot < 25) src = Wr1  + (size_t)(slot - 10) * 16384;
    else if (slot < 40) src = Wr2  + (size_t)(slot - 25) * 16384;
    else if (slot < 45) src = Wout + (size_t)(slot - 40) * 16384;
    else if (slot < 55) src = Wf1  + (size_t)(slot - 45) * 16384;
    else                src = Wf2  + (size_t)(slot - 55) * 16384;

    int q = blockIdx.x * 128 + threadIdx.x;   // 0..4095
    int l = q & 31, t = (q >> 5) & 15, s = q >> 9;
    int n = 8 * t + (l >> 2);
    int k0 = 16 * s + 2 * (l & 3);

    float w0 = src[(k0 + 0) * 128 + n];
    float w1 = src[(k0 + 1) * 128 + n];
    float w8 = src[(k0 + 8) * 128 + n];
    float w9 = src[(k0 + 9) * 128 + n];
    uint4 o;
    split2(w0, w1, o.x, o.z);
    split2(w8, w9, o.y, o.w);
    g_wfrag[(size_t)slot * 4096 + q] = o;
}

__global__ void wgfrag_k(const float* __restrict__ Wg)
{
    int slot = blockIdx.y;
    const float* src = Wg + (size_t)slot * KDIM * FDIM;
    int q = blockIdx.x * 128 + threadIdx.x;   // 0..2047
    int l = q & 31, t = (q >> 5) & 15, s = q >> 9;   // s 0..3
    int n = 8 * t + (l >> 2);
    int k0 = 16 * s + 2 * (l & 3);
    float w0 = src[(k0 + 0) * 128 + n];
    float w1 = src[(k0 + 1) * 128 + n];
    float w8 = src[(k0 + 8) * 128 + n];
    float w9 = src[(k0 + 9) * 128 + n];
    uint4 o;
    split2(w0, w1, o.x, o.z);
    split2(w8, w9, o.y, o.w);
    g_gfrag[(size_t)slot * 2048 + q] = o;
}

// ---------------------------------------------------------------------------
// Fused xi/xj GEMM (R12 config)
// ---------------------------------------------------------------------------
__global__ __launch_bounds__(128, 2)
void tmma2_k(const float* __restrict__ X,
             const uint4* __restrict__ WF1, const float* __restrict__ b1, float* __restrict__ Y1,
             const uint4* __restrict__ WF2, const float* __restrict__ b2, float* __restrict__ Y2,
             int M)
{
    const int tid = threadIdx.x;
    const int w = tid >> 5, l = tid & 31;
    const int c = l & 3, g = l >> 2;
    const int r0 = blockIdx.x * 64 + w * 16 + g;
    const int r1 = r0 + 8;
    const float* xr0 = X + (size_t)min(r0, M - 1) * FDIM;
    const float* xr1 = X + (size_t)min(r1, M - 1) * FDIM;

    uint32_t ahi[8][4], alo[8][4];
#pragma unroll
    for (int s = 0; s < 8; s++) {
        int col0 = 16 * s + 2 * c;
        float2 v00 = *(const float2*)(xr0 + col0);
        float2 v10 = *(const float2*)(xr1 + col0);
        float2 v01 = *(const float2*)(xr0 + col0 + 8);
        float2 v11 = *(const float2*)(xr1 + col0 + 8);
        v00.x = sspf(v00.x); v00.y = sspf(v00.y);
        v10.x = sspf(v10.x); v10.y = sspf(v10.y);
        v01.x = sspf(v01.x); v01.y = sspf(v01.y);
        v11.x = sspf(v11.x); v11.y = sspf(v11.y);
        split2(v00.x, v00.y, ahi[s][0], alo[s][0]);
        split2(v10.x, v10.y, ahi[s][1], alo[s][1]);
        split2(v01.x, v01.y, ahi[s][2], alo[s][2]);
        split2(v11.x, v11.y, ahi[s][3], alo[s][3]);
    }

    const bool ok0 = (r0 < M), ok1 = (r1 < M);

#pragma unroll
    for (int m = 0; m < 2; m++) {
        const uint4* WF = m ? WF2 : WF1;
        const float* bias = m ? b2 : b1;
        float* Y = m ? Y2 : Y1;
#pragma unroll
        for (int t = 0; t < 16; t++) {
            float d0 = 0.f, d1 = 0.f, d2 = 0.f, d3 = 0.f;
#pragma unroll
            for (int s = 0; s < 8; s++) {
                uint4 b = WF[(size_t)((s * 16 + t) * 32 + l)];
                MMA3(d0, d1, d2, d3, ahi[s], alo[s], b);
            }
            const int col = 8 * t + 2 * c;
            float2 bv = *(const float2*)(bias + col);
            float2 o0, o1;
            o0.x = sspf(d0 + bv.x); o0.y = sspf(d1 + bv.y);
            o1.x = sspf(d2 + bv.x); o1.y = sspf(d3 + bv.y);
            if (ok0) *(float2*)(Y + (size_t)r0 * FDIM + col) = o0;
            if (ok1) *(float2*)(Y + (size_t)r1 * FDIM + col) = o1;
        }
    }
}

// ---------------------------------------------------------------------------
// Tensor-core GEMM (R12 config): EPI=0 ssp, EPI=2 gated skip
// ---------------------------------------------------------------------------
template <int PRE, int EPI>
__global__ __launch_bounds__(128, 2)
void tmma_k(const float* __restrict__ X, const uint4* __restrict__ WF,
            const float* __restrict__ bias, const float* __restrict__ R,
            const float* __restrict__ U, float* __restrict__ Y, int M)
{
    const int tid = threadIdx.x;
    const int w = tid >> 5, l = tid & 31;
    const int c = l & 3, g = l >> 2;
    const int r0 = blockIdx.x * 64 + w * 16 + g;
    const int r1 = r0 + 8;
    const float* xr0 = X + (size_t)min(r0, M - 1) * FDIM;
    const float* xr1 = X + (size_t)min(r1, M - 1) * FDIM;

    uint32_t ahi[8][4], alo[8][4];
#pragma unroll
    for (int s = 0; s < 8; s++) {
        int col0 = 16 * s + 2 * c;
        float2 v00 = *(const float2*)(xr0 + col0);
        float2 v10 = *(const float2*)(xr1 + col0);
        float2 v01 = *(const float2*)(xr0 + col0 + 8);
        float2 v11 = *(const float2*)(xr1 + col0 + 8);
        if (PRE) {
            v00.x = sspf(v00.x); v00.y = sspf(v00.y);
            v10.x = sspf(v10.x); v10.y = sspf(v10.y);
            v01.x = sspf(v01.x); v01.y = sspf(v01.y);
            v11.x = sspf(v11.x); v11.y = sspf(v11.y);
        }
        split2(v00.x, v00.y, ahi[s][0], alo[s][0]);
        split2(v10.x, v10.y, ahi[s][1], alo[s][1]);
        split2(v01.x, v01.y, ahi[s][2], alo[s][2]);
        split2(v11.x, v11.y, ahi[s][3], alo[s][3]);
    }

    const bool ok0 = (r0 < M), ok1 = (r1 < M);

#pragma unroll
    for (int t = 0; t < 16; t++) {
        float d0 = 0.f, d1 = 0.f, d2 = 0.f, d3 = 0.f;
#pragma unroll
        for (int s = 0; s < 8; s++) {
            uint4 b = WF[(size_t)((s * 16 + t) * 32 + l)];
            MMA3(d0, d1, d2, d3, ahi[s], alo[s], b);
        }
        const int col = 8 * t + 2 * c;
        float2 bv = *(const float2*)(bias + col);
        d0 += bv.x; d1 += bv.y; d2 += bv.x; d3 += bv.y;

        float2 o0, o1;
        if (EPI == 0) {
            o0.x = sspf(d0); o0.y = sspf(d1);
            o1.x = sspf(d2); o1.y = sspf(d3);
        } else {
            float2 uv = *(const float2*)(U + col);
            float2 rv0 = ok0 ? *(const float2*)(R + (size_t)r0 * FDIM + col) : make_float2(0.f, 0.f);
            float2 rv1 = ok1 ? *(const float2*)(R + (size_t)r1 * FDIM + col) : make_float2(0.f, 0.f);
            o0.x = fmaf(uv.x, rv0.x, d0); o0.y = fmaf(uv.y, rv0.y, d1);
            o1.x = fmaf(uv.x, rv1.x, d2); o1.y = fmaf(uv.y, rv1.y, d3);
        }
        if (ok0) *(float2*)(Y + (size_t)r0 * FDIM + col) = o0;
        if (ok1) *(float2*)(Y + (size_t)r1 * FDIM + col) = o1;
    }
}

// ---------------------------------------------------------------------------
// Fused residual layer (R12 config): Y = X + ssp(ssp(X)@W1+b1)@W2 + b2
// ---------------------------------------------------------------------------
__global__ __launch_bounds__(128, 2)
void rsd_k(const float* __restrict__ X,
           const uint4* __restrict__ WF1, const float* __restrict__ b1,
           const uint4* __restrict__ WF2, const float* __restrict__ b2,
           float* __restrict__ Y, int M)
{
    const int tid = threadIdx.x;
    const int w = tid >> 5, l = tid & 31;
    const int c = l & 3, g = l >> 2;
    const int r0 = blockIdx.x * 64 + w * 16 + g;
    const int r1 = r0 + 8;
    const float* xr0 = X + (size_t)min(r0, M - 1) * FDIM;
    const float* xr1 = X + (size_t)min(r1, M - 1) * FDIM;

    uint32_t ahi[8][4], alo[8][4];
#pragma unroll
    for (int s = 0; s < 8; s++) {
        int col0 = 16 * s + 2 * c;
        float2 v00 = *(const float2*)(xr0 + col0);
        float2 v10 = *(const float2*)(xr1 + col0);
        float2 v01 = *(const float2*)(xr0 + col0 + 8);
        float2 v11 = *(const float2*)(xr1 + col0 + 8);
        v00.x = sspf(v00.x); v00.y = sspf(v00.y);
        v10.x = sspf(v10.x); v10.y = sspf(v10.y);
        v01.x = sspf(v01.x); v01.y = sspf(v01.y);
        v11.x = sspf(v11.x); v11.y = sspf(v11.y);
        split2(v00.x, v00.y, ahi[s][0], alo[s][0]);
        split2(v10.x, v10.y, ahi[s][1], alo[s][1]);
        split2(v01.x, v01.y, ahi[s][2], alo[s][2]);
        split2(v11.x, v11.y, ahi[s][3], alo[s][3]);
    }

    // GEMM1 with immediate repack of ssp(z) pairs into GEMM2 A-fragments
    uint32_t zhi[8][4], zlo[8][4];
    float zb0 = 0.f, zb1 = 0.f, zb2 = 0.f, zb3 = 0.f;
#pragma unroll
    for (int t = 0; t < 16; t++) {
        float d0 = 0.f, d1 = 0.f, d2 = 0.f, d3 = 0.f;
#pragma unroll
        for (int s = 0; s < 8; s++) {
            uint4 b = WF1[(size_t)((s * 16 + t) * 32 + l)];
            MMA3(d0, d1, d2, d3, ahi[s], alo[s], b);
        }
        const int col = 8 * t + 2 * c;
        float2 bv = *(const float2*)(b1 + col);
        d0 = sspf(d0 + bv.x); d1 = sspf(d1 + bv.y);
        d2 = sspf(d2 + bv.x); d3 = sspf(d3 + bv.y);
        if ((t & 1) == 0) {
            zb0 = d0; zb1 = d1; zb2 = d2; zb3 = d3;
        } else {
            const int s2 = t >> 1;
            split2(zb0, zb1, zhi[s2][0], zlo[s2][0]);
            split2(zb2, zb3, zhi[s2][1], zlo[s2][1]);
            split2(d0, d1, zhi[s2][2], zlo[s2][2]);
            split2(d2, d3, zhi[s2][3], zlo[s2][3]);
        }
    }

    const bool ok0 = (r0 < M), ok1 = (r1 < M);

    // GEMM2 + residual epilogue
#pragma unroll
    for (int t = 0; t < 16; t++) {
        float d0 = 0.f, d1 = 0.f, d2 = 0.f, d3 = 0.f;
#pragma unroll
        for (int s = 0; s < 8; s++) {
            uint4 b = WF2[(size_t)((s * 16 + t) * 32 + l)];
            MMA3(d0, d1, d2, d3, zhi[s], zlo[s], b);
        }
        const int col = 8 * t + 2 * c;
        float2 bv = *(const float2*)(b2 + col);
        float2 rv0 = ok0 ? *(const float2*)(X + (size_t)r0 * FDIM + col) : make_float2(0.f, 0.f);
        float2 rv1 = ok1 ? *(const float2*)(X + (size_t)r1 * FDIM + col) : make_float2(0.f, 0.f);
        float2 o0, o1;
        o0.x = rv0.x + d0 + bv.x; o0.y = rv0.y + d1 + bv.y;
        o1.x = rv1.x + d2 + bv.x; o1.y = rv1.y + d3 + bv.y;
        if (ok0) *(float2*)(Y + (size_t)r0 * FDIM + col) = o0;
        if (ok1) *(float2*)(Y + (size_t)r1 * FDIM + col) = o1;
    }
}

// ---------------------------------------------------------------------------
// Warp-specialized message pass: 256 threads, reg-capped to 2 CTAs/SM.
//   warps 0-3 (producer): stage desc (double-buffered), MMA filter -> gsm[buf]
//   warps 4-7 (consumer): gathers issued BEFORE waiting on full-barrier.
// Named barriers: full{0,1} = 1,2 ; empty{0,1} = 3,4 ; producer stage = 5.
// ---------------------------------------------------------------------------
#define MSG_PPB 512
#define DESC_P 68
#define GSM_P 132

__global__ __launch_bounds__(256, 2)
void msgmma_k(const float* __restrict__ cutoffs, const float* __restrict__ rbfs,
              const int* __restrict__ idx_i, const int* __restrict__ idx_j,
              const uint4* __restrict__ GF, const float* __restrict__ xj,
              float* __restrict__ m, int npairs)
{
    __shared__ __align__(16) float desc[2][32][DESC_P];
    __shared__ __align__(16) float gsm[2][32][GSM_P];

    const int tid = threadIdx.x;
    const int p0 = blockIdx.x * MSG_PPB;
    const int pend = min(p0 + MSG_PPB, npairs);

    if (tid < 128) {
        // ------------------------ producer ------------------------
        const int t = tid;
        const int w = t >> 5, l = t & 31;
        const int c = l & 3, g = l >> 2;
        int chunk = 0;
        for (int base = p0; base < pend; base += 32, chunk++) {
            const int b = chunk & 1;
            const int ns = min(32, pend - base);
            if (chunk >= 2) BAR_SYNC(3 + b, 256);     // gsm[b] consumed

            // stage desc[b] = cutoff * rbf
            for (int li = t; li < ns * 16; li += 128) {
                int s = li >> 4, v = li & 15;
                float cf = cutoffs[base + s];
                float4 r = *(const float4*)&rbfs[(size_t)(base + s) * KDIM + v * 4];
                r.x *= cf; r.y *= cf; r.z *= cf; r.w *= cf;
                *(float4*)&desc[b][s][v * 4] = r;
            }
            BAR_SYNC(5, 128);   // desc[b] visible; also fences desc[b] reuse at chunk+2

            // frag build (2 m-tiles x 4 k-steps)
            uint32_t ahi[2][4][4], alo[2][4][4];
#pragma unroll
            for (int mt = 0; mt < 2; mt++) {
                int rg = mt * 16 + g;
#pragma unroll
                for (int s = 0; s < 4; s++) {
                    int k0 = 16 * s + 2 * c;
                    float2 v00 = *(const float2*)&desc[b][rg][k0];
                    float2 v10 = *(const float2*)&desc[b][rg + 8][k0];
                    float2 v01 = *(const float2*)&desc[b][rg][k0 + 8];
                    float2 v11 = *(const float2*)&desc[b][rg + 8][k0 + 8];
                    split2(v00.x, v00.y, ahi[mt][s][0], alo[mt][s][0]);
                    split2(v10.x, v10.y, ahi[mt][s][1], alo[mt][s][1]);
                    split2(v01.x, v01.y, ahi[mt][s][2], alo[mt][s][2]);
                    split2(v11.x, v11.y, ahi[mt][s][3], alo[mt][s][3]);
                }
            }
            // MMA: warp w covers n-tiles 4w..4w+3; 2-quad accumulators (8+4 chains)
#pragma unroll
            for (int j = 0; j < 4; j++) {
                const int tt = 4 * w + j;
                const int col = 8 * tt + 2 * c;
#pragma unroll
                for (int mt = 0; mt < 2; mt++) {
                    float e[4] = {0.f, 0.f, 0.f, 0.f};
                    float f[4] = {0.f, 0.f, 0.f, 0.f};
#pragma unroll
                    for (int s = 0; s < 4; s++) {
                        uint4 bb = GF[(size_t)((s * 16 + tt) * 32 + l)];
                        MMA3T(e, f, ahi[mt][s], alo[mt][s], bb);
                    }
                    int rg = mt * 16 + g;
                    *(float2*)&gsm[b][rg][col] = make_float2(e[0] + f[0], e[1] + f[1]);
                    *(float2*)&gsm[b][rg + 8][col] = make_float2(e[2] + f[2], e[3] + f[3]);
                }
            }
            BAR_ARRIVE(1 + b, 256);                    // gsm[b] full
        }
    } else {
        // ------------------------ consumer ------------------------
        const int t = tid - 128;                       // feature index
        const int lane = t & 31;
        float acc = 0.0f;
        int prev = -1;
        int chunk = 0;
        for (int base = p0; base < pend; base += 32, chunk++) {
            const int b = chunk & 1;
            const int ns = min(32, pend - base);
            // load indices + issue gathers BEFORE waiting (overlap producer MMA)
            const int gi = base + min(lane, ns - 1);
            int sjr = idx_j[gi];
            int sir = idx_i[gi];
            float xv[32];
#pragma unroll
            for (int s = 0; s < 32; s++) {
                int j = __shfl_sync(0xFFFFFFFFu, sjr, s);
                xv[s] = xj[(size_t)j * FDIM + t];
            }
            BAR_SYNC(1 + b, 256);                      // wait gsm[b] full
#pragma unroll
            for (int s = 0; s < 32; s++) {
                if (s < ns) {
                    int i = __shfl_sync(0xFFFFFFFFu, sir, s);
                    if (i != prev) {
                        if (prev >= 0) atomicAdd(&m[(size_t)prev * FDIM + t], acc);
                        acc = 0.0f;
                        prev = i;
                    }
                    acc = fmaf(gsm[b][s][t], xv[s], acc);
                }
            }
            BAR_ARRIVE(3 + b, 256);                    // gsm[b] empty
        }
        if (prev >= 0) atomicAdd(&m[(size_t)prev * FDIM + t], acc);
    }
}

// ---------------------------------------------------------------------------
extern "C" void kernel_launch(void* const* d_in, const int* in_sizes, int n_in,
                              void* d_out, int out_size)
{
    const float* features = (const float*)d_in[0];
    const float* cutoffs  = (const float*)d_in[1];
    const float* rbfs     = (const float*)d_in[2];
    const int*   idx_i    = (const int*)d_in[3];
    const int*   idx_j    = (const int*)d_in[4];
    const float* Wg   = (const float*)d_in[5];
    const float* bi   = (const float*)d_in[7];
    const float* bj   = (const float*)d_in[9];
    const float* br1  = (const float*)d_in[11];
    const float* br2  = (const float*)d_in[13];
    const float* bout = (const float*)d_in[15];
    const float* u    = (const float*)d_in[16];
    const float* bf1  = (const float*)d_in[18];
    const float* bf2  = (const float*)d_in[20];
    const int npairs = in_sizes[1];
    float* out = (float*)d_out;

    float *xjp, *mp;
    uint4 *wfrag, *gfrag;
    cudaGetSymbolAddress((void**)&xjp, g_xj);
    cudaGetSymbolAddress((void**)&mp,  g_m);
    cudaGetSymbolAddress((void**)&wfrag, g_wfrag);
    cudaGetSymbolAddress((void**)&gfrag, g_gfrag);

    const int gemmGrid = (NATOMS + 63) / 64;
    const int msgGrid = (npairs + MSG_PPB - 1) / MSG_PPB;

    // prepasses (cheap; once per launch)
    wfrag_k<<<dim3(32, NWMAT), 128>>>((const float*)d_in[6], (const float*)d_in[8],
                                      (const float*)d_in[10], (const float*)d_in[12],
                                      (const float*)d_in[14], (const float*)d_in[17],
                                      (const float*)d_in[19]);
    wgfrag_k<<<dim3(16, NB), 128>>>(Wg);

    auto WFr = [&](int slot) { return wfrag + (size_t)slot * 4096; };

    const float* x = features;
    for (int b = 0; b < NB; b++) {
        float* xout = out + (size_t)b * NATOMS * FDIM;

        // m = xi = ssp(ssp(x)@Wi+bi);  xj = ssp(ssp(x)@Wj+bj)   (fused)
        tmma2_k<<<gemmGrid, 128>>>(x, WFr(b), bi + b * FDIM, mp,
                                   WFr(5 + b), bj + b * FDIM, xjp, NATOMS);
        // m += segment_sum( (desc @ Wg) * xj[idx_j], idx_i )  (warp-specialized)
        msgmma_k<<<msgGrid, 256>>>(cutoffs, rbfs, idx_i, idx_j,
                                   gfrag + (size_t)b * 2048, xjp, mp, npairs);
        // interaction residuals (fused pairs, in-place)
        for (int r = 0; r < NRI; r++) {
            int s1 = 10 + b * NRI + r, s2 = 25 + b * NRI + r;
            rsd_k<<<gemmGrid, 128>>>(mp, WFr(s1), br1 + (size_t)(b * NRI + r) * FDIM,
                                     WFr(s2), br2 + (size_t)(b * NRI + r) * FDIM, mp, NATOMS);
        }
        // x' = u*x + ssp(m) @ Wout + bout
        tmma_k<1, 2><<<gemmGrid, 128>>>(mp, WFr(40 + b), bout + b * FDIM,
                                        x, u + b * FDIM, xout, NATOMS);
        // feature residuals (fused pairs, in-place on output slab)
        for (int r = 0; r < NRF; r++) {
            int s1 = 45 + b * NRF + r, s2 = 55 + b * NRF + r;
            rsd_k<<<gemmGrid, 128>>>(xout, WFr(s1), bf1 + (size_t)(b * NRF + r) * FDIM,
                                     WFr(s2), bf2 + (size_t)(b * NRF + r) * FDIM, xout, NATOMS);
        }
        x = xout;
    }
}

// round 17
// speedup vs baseline: 2.1470x; 1.5569x over previous
#include <cuda_runtime.h>
#include <cuda_bf16.h>
#include <cstdint>

#define NATOMS 50000
#define FDIM 128
#define KDIM 64
#define NB 5
#define NRI 3
#define NRF 2
#define NWMAT 65   // 5 Wi + 5 Wj + 15 Wr1 + 15 Wr2 + 5 Wout + 10 Wf1 + 10 Wf2

// Scratch (allocation-free rule: __device__ globals)
__device__ float g_xj[NATOMS * FDIM];
__device__ float g_m [NATOMS * FDIM];
// Per-lane prepacked B fragments: [slot][s(8)][t(16)][lane(32)] = uint4{bhi0,bhi1,blo0,blo1}
__device__ uint4 g_wfrag[(size_t)NWMAT * 4096];
// Wg fragments: [slot(5)][s(4)][t(16)][lane(32)]
__device__ uint4 g_gfrag[(size_t)NB * 2048];

__device__ __forceinline__ float sspf(float x) {
    return fmaxf(x, 0.0f) + log1pf(expf(-fabsf(x))) - 0.69314718055994530942f;
}

// ---- bf16x2 pack: low 16 bits = bf16(lo), high = bf16(hi) ----
__device__ __forceinline__ uint32_t pack_bf(float lo, float hi) {
    uint32_t r;
    asm("cvt.rn.bf16x2.f32 %0, %1, %2;" : "=r"(r) : "f"(hi), "f"(lo));
    return r;
}
// split float2 -> bf16x2 hi fragment + bf16x2 lo (residual) fragment
__device__ __forceinline__ void split2(float a, float b, uint32_t& h, uint32_t& l) {
    h = pack_bf(a, b);
    float h0 = __uint_as_float(h << 16);
    float h1 = __uint_as_float(h & 0xFFFF0000u);
    l = pack_bf(a - h0, b - h1);
}

// m16n8k16 row.col f32.bf16.bf16.f32
#define MMA_BF16(d0, d1, d2, d3, a0, a1, a2, a3, b0, b1)                     \
    asm volatile("mma.sync.aligned.m16n8k16.row.col.f32.bf16.bf16.f32 "      \
                 "{%0,%1,%2,%3},{%4,%5,%6,%7},{%8,%9},{%0,%1,%2,%3};"        \
                 : "+f"(d0), "+f"(d1), "+f"(d2), "+f"(d3)                    \
                 : "r"(a0), "r"(a1), "r"(a2), "r"(a3), "r"(b0), "r"(b1))

// 3-term split MMA, single accumulator (R12 proven config)
#define MMA3(d0, d1, d2, d3, AH, AL, b)                                          \
    do {                                                                         \
        MMA_BF16(d0, d1, d2, d3, AH[0], AH[1], AH[2], AH[3], (b).x, (b).y);      \
        MMA_BF16(d0, d1, d2, d3, AL[0], AL[1], AL[2], AL[3], (b).x, (b).y);      \
        MMA_BF16(d0, d1, d2, d3, AH[0], AH[1], AH[2], AH[3], (b).z, (b).w);      \
    } while (0)

// named barriers (producer/consumer handshake)
#define BAR_SYNC(id, cnt)   asm volatile("bar.sync %0, %1;"   :: "r"(id), "r"(cnt) : "memory")
#define BAR_ARRIVE(id, cnt) asm volatile("bar.arrive %0, %1;" :: "r"(id), "r"(cnt) : "memory")

// ---------------------------------------------------------------------------
// Weight prepasses
// ---------------------------------------------------------------------------
__global__ void wfrag_k(const float* __restrict__ Wi, const float* __restrict__ Wj,
                        const float* __restrict__ Wr1, const float* __restrict__ Wr2,
                        const float* __restrict__ Wout, const float* __restrict__ Wf1,
                        const float* __restrict__ Wf2)
{
    int slot = blockIdx.y;
    const float* src;
    if (slot < 5)       src = Wi   + (size_t)slot * 16384;
    else if (slot < 10) src = Wj   + (size_t)(slot - 5) * 16384;
    else if (slot < 25) src = Wr1  + (size_t)(slot - 10) * 16384;
    else if (slot < 40) src = Wr2  + (size_t)(slot - 25) * 16384;
    else if (slot < 45) src = Wout + (size_t)(slot - 40) * 16384;
    else if (slot < 55) src = Wf1  + (size_t)(slot - 45) * 16384;
    else                src = Wf2  + (size_t)(slot - 55) * 16384;

    int q = blockIdx.x * 128 + threadIdx.x;   // 0..4095
    int l = q & 31, t = (q >> 5) & 15, s = q >> 9;
    int n = 8 * t + (l >> 2);
    int k0 = 16 * s + 2 * (l & 3);

    float w0 = src[(k0 + 0) * 128 + n];
    float w1 = src[(k0 + 1) * 128 + n];
    float w8 = src[(k0 + 8) * 128 + n];
    float w9 = src[(k0 + 9) * 128 + n];
    uint4 o;
    split2(w0, w1, o.x, o.z);
    split2(w8, w9, o.y, o.w);
    g_wfrag[(size_t)slot * 4096 + q] = o;
}

__global__ void wgfrag_k(const float* __restrict__ Wg)
{
    int slot = blockIdx.y;
    const float* src = Wg + (size_t)slot * KDIM * FDIM;
    int q = blockIdx.x * 128 + threadIdx.x;   // 0..2047
    int l = q & 31, t = (q >> 5) & 15, s = q >> 9;   // s 0..3
    int n = 8 * t + (l >> 2);
    int k0 = 16 * s + 2 * (l & 3);
    float w0 = src[(k0 + 0) * 128 + n];
    float w1 = src[(k0 + 1) * 128 + n];
    float w8 = src[(k0 + 8) * 128 + n];
    float w9 = src[(k0 + 9) * 128 + n];
    uint4 o;
    split2(w0, w1, o.x, o.z);
    split2(w8, w9, o.y, o.w);
    g_gfrag[(size_t)slot * 2048 + q] = o;
}

// ---------------------------------------------------------------------------
// Fused xi/xj GEMM (R12 config)
// ---------------------------------------------------------------------------
__global__ __launch_bounds__(128, 2)
void tmma2_k(const float* __restrict__ X,
             const uint4* __restrict__ WF1, const float* __restrict__ b1, float* __restrict__ Y1,
             const uint4* __restrict__ WF2, const float* __restrict__ b2, float* __restrict__ Y2,
             int M)
{
    const int tid = threadIdx.x;
    const int w = tid >> 5, l = tid & 31;
    const int c = l & 3, g = l >> 2;
    const int r0 = blockIdx.x * 64 + w * 16 + g;
    const int r1 = r0 + 8;
    const float* xr0 = X + (size_t)min(r0, M - 1) * FDIM;
    const float* xr1 = X + (size_t)min(r1, M - 1) * FDIM;

    uint32_t ahi[8][4], alo[8][4];
#pragma unroll
    for (int s = 0; s < 8; s++) {
        int col0 = 16 * s + 2 * c;
        float2 v00 = *(const float2*)(xr0 + col0);
        float2 v10 = *(const float2*)(xr1 + col0);
        float2 v01 = *(const float2*)(xr0 + col0 + 8);
        float2 v11 = *(const float2*)(xr1 + col0 + 8);
        v00.x = sspf(v00.x); v00.y = sspf(v00.y);
        v10.x = sspf(v10.x); v10.y = sspf(v10.y);
        v01.x = sspf(v01.x); v01.y = sspf(v01.y);
        v11.x = sspf(v11.x); v11.y = sspf(v11.y);
        split2(v00.x, v00.y, ahi[s][0], alo[s][0]);
        split2(v10.x, v10.y, ahi[s][1], alo[s][1]);
        split2(v01.x, v01.y, ahi[s][2], alo[s][2]);
        split2(v11.x, v11.y, ahi[s][3], alo[s][3]);
    }

    const bool ok0 = (r0 < M), ok1 = (r1 < M);

#pragma unroll
    for (int m = 0; m < 2; m++) {
        const uint4* WF = m ? WF2 : WF1;
        const float* bias = m ? b2 : b1;
        float* Y = m ? Y2 : Y1;
#pragma unroll
        for (int t = 0; t < 16; t++) {
            float d0 = 0.f, d1 = 0.f, d2 = 0.f, d3 = 0.f;
#pragma unroll
            for (int s = 0; s < 8; s++) {
                uint4 b = WF[(size_t)((s * 16 + t) * 32 + l)];
                MMA3(d0, d1, d2, d3, ahi[s], alo[s], b);
            }
            const int col = 8 * t + 2 * c;
            float2 bv = *(const float2*)(bias + col);
            float2 o0, o1;
            o0.x = sspf(d0 + bv.x); o0.y = sspf(d1 + bv.y);
            o1.x = sspf(d2 + bv.x); o1.y = sspf(d3 + bv.y);
            if (ok0) *(float2*)(Y + (size_t)r0 * FDIM + col) = o0;
            if (ok1) *(float2*)(Y + (size_t)r1 * FDIM + col) = o1;
        }
    }
}

// ---------------------------------------------------------------------------
// Tensor-core GEMM (R12 config): EPI=0 ssp, EPI=2 gated skip
// ---------------------------------------------------------------------------
template <int PRE, int EPI>
__global__ __launch_bounds__(128, 2)
void tmma_k(const float* __restrict__ X, const uint4* __restrict__ WF,
            const float* __restrict__ bias, const float* __restrict__ R,
            const float* __restrict__ U, float* __restrict__ Y, int M)
{
    const int tid = threadIdx.x;
    const int w = tid >> 5, l = tid & 31;
    const int c = l & 3, g = l >> 2;
    const int r0 = blockIdx.x * 64 + w * 16 + g;
    const int r1 = r0 + 8;
    const float* xr0 = X + (size_t)min(r0, M - 1) * FDIM;
    const float* xr1 = X + (size_t)min(r1, M - 1) * FDIM;

    uint32_t ahi[8][4], alo[8][4];
#pragma unroll
    for (int s = 0; s < 8; s++) {
        int col0 = 16 * s + 2 * c;
        float2 v00 = *(const float2*)(xr0 + col0);
        float2 v10 = *(const float2*)(xr1 + col0);
        float2 v01 = *(const float2*)(xr0 + col0 + 8);
        float2 v11 = *(const float2*)(xr1 + col0 + 8);
        if (PRE) {
            v00.x = sspf(v00.x); v00.y = sspf(v00.y);
            v10.x = sspf(v10.x); v10.y = sspf(v10.y);
            v01.x = sspf(v01.x); v01.y = sspf(v01.y);
            v11.x = sspf(v11.x); v11.y = sspf(v11.y);
        }
        split2(v00.x, v00.y, ahi[s][0], alo[s][0]);
        split2(v10.x, v10.y, ahi[s][1], alo[s][1]);
        split2(v01.x, v01.y, ahi[s][2], alo[s][2]);
        split2(v11.x, v11.y, ahi[s][3], alo[s][3]);
    }

    const bool ok0 = (r0 < M), ok1 = (r1 < M);

#pragma unroll
    for (int t = 0; t < 16; t++) {
        float d0 = 0.f, d1 = 0.f, d2 = 0.f, d3 = 0.f;
#pragma unroll
        for (int s = 0; s < 8; s++) {
            uint4 b = WF[(size_t)((s * 16 + t) * 32 + l)];
            MMA3(d0, d1, d2, d3, ahi[s], alo[s], b);
        }
        const int col = 8 * t + 2 * c;
        float2 bv = *(const float2*)(bias + col);
        d0 += bv.x; d1 += bv.y; d2 += bv.x; d3 += bv.y;

        float2 o0, o1;
        if (EPI == 0) {
            o0.x = sspf(d0); o0.y = sspf(d1);
            o1.x = sspf(d2); o1.y = sspf(d3);
        } else {
            float2 uv = *(const float2*)(U + col);
            float2 rv0 = ok0 ? *(const float2*)(R + (size_t)r0 * FDIM + col) : make_float2(0.f, 0.f);
            float2 rv1 = ok1 ? *(const float2*)(R + (size_t)r1 * FDIM + col) : make_float2(0.f, 0.f);
            o0.x = fmaf(uv.x, rv0.x, d0); o0.y = fmaf(uv.y, rv0.y, d1);
            o1.x = fmaf(uv.x, rv1.x, d2); o1.y = fmaf(uv.y, rv1.y, d3);
        }
        if (ok0) *(float2*)(Y + (size_t)r0 * FDIM + col) = o0;
        if (ok1) *(float2*)(Y + (size_t)r1 * FDIM + col) = o1;
    }
}

// ---------------------------------------------------------------------------
// Fused residual layer (R12 config): Y = X + ssp(ssp(X)@W1+b1)@W2 + b2
// ---------------------------------------------------------------------------
__global__ __launch_bounds__(128, 2)
void rsd_k(const float* __restrict__ X,
           const uint4* __restrict__ WF1, const float* __restrict__ b1,
           const uint4* __restrict__ WF2, const float* __restrict__ b2,
           float* __restrict__ Y, int M)
{
    const int tid = threadIdx.x;
    const int w = tid >> 5, l = tid & 31;
    const int c = l & 3, g = l >> 2;
    const int r0 = blockIdx.x * 64 + w * 16 + g;
    const int r1 = r0 + 8;
    const float* xr0 = X + (size_t)min(r0, M - 1) * FDIM;
    const float* xr1 = X + (size_t)min(r1, M - 1) * FDIM;

    uint32_t ahi[8][4], alo[8][4];
#pragma unroll
    for (int s = 0; s < 8; s++) {
        int col0 = 16 * s + 2 * c;
        float2 v00 = *(const float2*)(xr0 + col0);
        float2 v10 = *(const float2*)(xr1 + col0);
        float2 v01 = *(const float2*)(xr0 + col0 + 8);
        float2 v11 = *(const float2*)(xr1 + col0 + 8);
        v00.x = sspf(v00.x); v00.y = sspf(v00.y);
        v10.x = sspf(v10.x); v10.y = sspf(v10.y);
        v01.x = sspf(v01.x); v01.y = sspf(v01.y);
        v11.x = sspf(v11.x); v11.y = sspf(v11.y);
        split2(v00.x, v00.y, ahi[s][0], alo[s][0]);
        split2(v10.x, v10.y, ahi[s][1], alo[s][1]);
        split2(v01.x, v01.y, ahi[s][2], alo[s][2]);
        split2(v11.x, v11.y, ahi[s][3], alo[s][3]);
    }

    // GEMM1 with immediate repack of ssp(z) pairs into GEMM2 A-fragments
    uint32_t zhi[8][4], zlo[8][4];
    float zb0 = 0.f, zb1 = 0.f, zb2 = 0.f, zb3 = 0.f;
#pragma unroll
    for (int t = 0; t < 16; t++) {
        float d0 = 0.f, d1 = 0.f, d2 = 0.f, d3 = 0.f;
#pragma unroll
        for (int s = 0; s < 8; s++) {
            uint4 b = WF1[(size_t)((s * 16 + t) * 32 + l)];
            MMA3(d0, d1, d2, d3, ahi[s], alo[s], b);
        }
        const int col = 8 * t + 2 * c;
        float2 bv = *(const float2*)(b1 + col);
        d0 = sspf(d0 + bv.x); d1 = sspf(d1 + bv.y);
        d2 = sspf(d2 + bv.x); d3 = sspf(d3 + bv.y);
        if ((t & 1) == 0) {
            zb0 = d0; zb1 = d1; zb2 = d2; zb3 = d3;
        } else {
            const int s2 = t >> 1;
            split2(zb0, zb1, zhi[s2][0], zlo[s2][0]);
            split2(zb2, zb3, zhi[s2][1], zlo[s2][1]);
            split2(d0, d1, zhi[s2][2], zlo[s2][2]);
            split2(d2, d3, zhi[s2][3], zlo[s2][3]);
        }
    }

    const bool ok0 = (r0 < M), ok1 = (r1 < M);

    // GEMM2 + residual epilogue
#pragma unroll
    for (int t = 0; t < 16; t++) {
        float d0 = 0.f, d1 = 0.f, d2 = 0.f, d3 = 0.f;
#pragma unroll
        for (int s = 0; s < 8; s++) {
            uint4 b = WF2[(size_t)((s * 16 + t) * 32 + l)];
            MMA3(d0, d1, d2, d3, zhi[s], zlo[s], b);
        }
        const int col = 8 * t + 2 * c;
        float2 bv = *(const float2*)(b2 + col);
        float2 rv0 = ok0 ? *(const float2*)(X + (size_t)r0 * FDIM + col) : make_float2(0.f, 0.f);
        float2 rv1 = ok1 ? *(const float2*)(X + (size_t)r1 * FDIM + col) : make_float2(0.f, 0.f);
        float2 o0, o1;
        o0.x = rv0.x + d0 + bv.x; o0.y = rv0.y + d1 + bv.y;
        o1.x = rv1.x + d2 + bv.x; o1.y = rv1.y + d3 + bv.y;
        if (ok0) *(float2*)(Y + (size_t)r0 * FDIM + col) = o0;
        if (ok1) *(float2*)(Y + (size_t)r1 * FDIM + col) = o1;
    }
}

// ---------------------------------------------------------------------------
// Warp-specialized message pass (R12 structure): 256 threads.
//   warps 0-3 (producer): stage desc, MMA filter -> gsm[buf] (double-buffered)
//   warps 4-7 (consumer): gathers issued BEFORE waiting on full-barrier.
// Named barriers: full{0,1} = 1,2 ; empty{0,1} = 3,4 ; producer-internal = 5.
// ---------------------------------------------------------------------------
#define MSG_PPB 512
#define DESC_P 68
#define GSM_P 132

__global__ __launch_bounds__(256, 2)
void msgmma_k(const float* __restrict__ cutoffs, const float* __restrict__ rbfs,
              const int* __restrict__ idx_i, const int* __restrict__ idx_j,
              const uint4* __restrict__ GF, const float* __restrict__ xj,
              float* __restrict__ m, int npairs)
{
    __shared__ __align__(16) float desc[32][DESC_P];
    __shared__ __align__(16) float gsm[2][32][GSM_P];

    const int tid = threadIdx.x;
    const int p0 = blockIdx.x * MSG_PPB;
    const int pend = min(p0 + MSG_PPB, npairs);

    if (tid < 128) {
        // ------------------------ producer ------------------------
        const int t = tid;
        const int w = t >> 5, l = t & 31;
        const int c = l & 3, g = l >> 2;
        int chunk = 0;
        for (int base = p0; base < pend; base += 32, chunk++) {
            const int b = chunk & 1;
            const int ns = min(32, pend - base);
            if (chunk >= 2) BAR_SYNC(3 + b, 256);     // gsm[b] consumed

            // stage desc = cutoff * rbf
            if (ns == 32) {
#pragma unroll
                for (int it = 0; it < 4; it++) {
                    int li = t + it * 128;
                    int s = li >> 4, v = li & 15;
                    float cf = cutoffs[base + s];
                    float4 r = *(const float4*)&rbfs[(size_t)(base + s) * KDIM + v * 4];
                    r.x *= cf; r.y *= cf; r.z *= cf; r.w *= cf;
                    *(float4*)&desc[s][v * 4] = r;
                }
            } else {
                for (int li = t; li < ns * 16; li += 128) {
                    int s = li >> 4, v = li & 15;
                    float cf = cutoffs[base + s];
                    float4 r = *(const float4*)&rbfs[(size_t)(base + s) * KDIM + v * 4];
                    r.x *= cf; r.y *= cf; r.z *= cf; r.w *= cf;
                    *(float4*)&desc[s][v * 4] = r;
                }
            }
            BAR_SYNC(5, 128);                          // desc visible to producers

            // frag build (2 m-tiles x 4 k-steps)
            uint32_t ahi[2][4][4], alo[2][4][4];
#pragma unroll
            for (int mt = 0; mt < 2; mt++) {
                int rg = mt * 16 + g;
#pragma unroll
                for (int s = 0; s < 4; s++) {
                    int k0 = 16 * s + 2 * c;
                    float2 v00 = *(const float2*)&desc[rg][k0];
                    float2 v10 = *(const float2*)&desc[rg + 8][k0];
                    float2 v01 = *(const float2*)&desc[rg][k0 + 8];
                    float2 v11 = *(const float2*)&desc[rg + 8][k0 + 8];
                    split2(v00.x, v00.y, ahi[mt][s][0], alo[mt][s][0]);
                    split2(v10.x, v10.y, ahi[mt][s][1], alo[mt][s][1]);
                    split2(v01.x, v01.y, ahi[mt][s][2], alo[mt][s][2]);
                    split2(v11.x, v11.y, ahi[mt][s][3], alo[mt][s][3]);
                }
            }
            // MMA: warp w covers n-tiles 4w..4w+3
#pragma unroll
            for (int j = 0; j < 4; j++) {
                const int tt = 4 * w + j;
                const int col = 8 * tt + 2 * c;
#pragma unroll
                for (int mt = 0; mt < 2; mt++) {
                    float d0 = 0.f, d1 = 0.f, d2 = 0.f, d3 = 0.f;
#pragma unroll
                    for (int s = 0; s < 4; s++) {
                        uint4 bb = GF[(size_t)((s * 16 + tt) * 32 + l)];
                        MMA3(d0, d1, d2, d3, ahi[mt][s], alo[mt][s], bb);
                    }
                    int rg = mt * 16 + g;
                    *(float2*)&gsm[b][rg][col] = make_float2(d0, d1);
                    *(float2*)&gsm[b][rg + 8][col] = make_float2(d2, d3);
                }
            }
            BAR_ARRIVE(1 + b, 256);                    // gsm[b] full
            BAR_SYNC(5, 128);                          // all producers done with desc
        }
    } else {
        // ------------------------ consumer ------------------------
        const int t = tid - 128;                       // feature index
        const int lane = t & 31;
        float acc = 0.0f;
        int prev = -1;
        int chunk = 0;
        for (int base = p0; base < pend; base += 32, chunk++) {
            const int b = chunk & 1;
            const int ns = min(32, pend - base);
            // load indices + issue gathers BEFORE waiting (overlap producer MMA)
            const int gi = base + min(lane, ns - 1);
            int sjr = idx_j[gi];
            int sir = idx_i[gi];
            float xv[32];
#pragma unroll
            for (int s = 0; s < 32; s++) {
                int j = __shfl_sync(0xFFFFFFFFu, sjr, s);
                xv[s] = xj[(size_t)j * FDIM + t];
            }
            BAR_SYNC(1 + b, 256);                      // wait gsm[b] full
            if (ns == 32) {
#pragma unroll
                for (int s = 0; s < 32; s++) {
                    int i = __shfl_sync(0xFFFFFFFFu, sir, s);
                    if (i != prev) {
                        if (prev >= 0) atomicAdd(&m[(size_t)prev * FDIM + t], acc);
                        acc = 0.0f;
                        prev = i;
                    }
                    acc = fmaf(gsm[b][s][t], xv[s], acc);
                }
            } else {
                for (int s = 0; s < ns; s++) {
                    int i = __shfl_sync(0xFFFFFFFFu, sir, s);
                    if (i != prev) {
                        if (prev >= 0) atomicAdd(&m[(size_t)prev * FDIM + t], acc);
                        acc = 0.0f;
                        prev = i;
                    }
                    acc = fmaf(gsm[b][s][t], xv[s], acc);
                }
            }
            BAR_ARRIVE(3 + b, 256);                    // gsm[b] empty
        }
        if (prev >= 0) atomicAdd(&m[(size_t)prev * FDIM + t], acc);
    }
}

// ---------------------------------------------------------------------------
extern "C" void kernel_launch(void* const* d_in, const int* in_sizes, int n_in,
                              void* d_out, int out_size)
{
    const float* features = (const float*)d_in[0];
    const float* cutoffs  = (const float*)d_in[1];
    const float* rbfs     = (const float*)d_in[2];
    const int*   idx_i    = (const int*)d_in[3];
    const int*   idx_j    = (const int*)d_in[4];
    const float* Wg   = (const float*)d_in[5];
    const float* bi   = (const float*)d_in[7];
    const float* bj   = (const float*)d_in[9];
    const float* br1  = (const float*)d_in[11];
    const float* br2  = (const float*)d_in[13];
    const float* bout = (const float*)d_in[15];
    const float* u    = (const float*)d_in[16];
    const float* bf1  = (const float*)d_in[18];
    const float* bf2  = (const float*)d_in[20];
    const int npairs = in_sizes[1];
    float* out = (float*)d_out;

    float *xjp, *mp;
    uint4 *wfrag, *gfrag;
    cudaGetSymbolAddress((void**)&xjp, g_xj);
    cudaGetSymbolAddress((void**)&mp,  g_m);
    cudaGetSymbolAddress((void**)&wfrag, g_wfrag);
    cudaGetSymbolAddress((void**)&gfrag, g_gfrag);

    const int gemmGrid = (NATOMS + 63) / 64;
    const int msgGrid = (npairs + MSG_PPB - 1) / MSG_PPB;

    // prepasses (cheap; once per launch)
    wfrag_k<<<dim3(32, NWMAT), 128>>>((const float*)d_in[6], (const float*)d_in[8],
                                      (const float*)d_in[10], (const float*)d_in[12],
                                      (const float*)d_in[14], (const float*)d_in[17],
                                      (const float*)d_in[19]);
    wgfrag_k<<<dim3(16, NB), 128>>>(Wg);

    auto WFr = [&](int slot) { return wfrag + (size_t)slot * 4096; };

    const float* x = features;
    for (int b = 0; b < NB; b++) {
        float* xout = out + (size_t)b * NATOMS * FDIM;

        // m = xi = ssp(ssp(x)@Wi+bi);  xj = ssp(ssp(x)@Wj+bj)   (fused)
        tmma2_k<<<gemmGrid, 128>>>(x, WFr(b), bi + b * FDIM, mp,
                                   WFr(5 + b), bj + b * FDIM, xjp, NATOMS);
        // m += segment_sum( (desc @ Wg) * xj[idx_j], idx_i )  (warp-specialized)
        msgmma_k<<<msgGrid, 256>>>(cutoffs, rbfs, idx_i, idx_j,
                                   gfrag + (size_t)b * 2048, xjp, mp, npairs);
        // interaction residuals (fused pairs, in-place)
        for (int r = 0; r < NRI; r++) {
            int s1 = 10 + b * NRI + r, s2 = 25 + b * NRI + r;
            rsd_k<<<gemmGrid, 128>>>(mp, WFr(s1), br1 + (size_t)(b * NRI + r) * FDIM,
                                     WFr(s2), br2 + (size_t)(b * NRI + r) * FDIM, mp, NATOMS);
        }
        // x' = u*x + ssp(m) @ Wout + bout
        tmma_k<1, 2><<<gemmGrid, 128>>>(mp, WFr(40 + b), bout + b * FDIM,
                                        x, u + b * FDIM, xout, NATOMS);
        // feature residuals (fused pairs, in-place on output slab)
        for (int r = 0; r < NRF; r++) {
            int s1 = 45 + b * NRF + r, s2 = 55 + b * NRF + r;
            rsd_k<<<gemmGrid, 128>>>(xout, WFr(s1), bf1 + (size_t)(b * NRF + r) * FDIM,
                                     WFr(s2), bf2 + (size_t)(b * NRF + r) * FDIM, xout, NATOMS);
        }
        x = xout;
    }
}